// round 3
// baseline (speedup 1.0000x reference)
#include <cuda_runtime.h>
#include <cuda_fp16.h>
#include <stdint.h>

#define B_ 256
#define R_ 192
#define C_ 96
#define O_ 16
#define I_ 20
#define BCH 16                  // batch elements per fused block
#define NCH (B_ / BCH)          // 16 chunks

// Scratch (allocation-free rule: __device__ globals)
__device__ __half g_uhat[(size_t)R_ * C_ * B_ * O_];  // [R][C][B][O] fp16 ~151MB
__device__ float  g_xT[(size_t)R_ * I_ * B_];         // [R][I][B] transposed x
__device__ float  g_part[2][NCH][R_][C_];             // agreement partials per iter

// ---- packed fp32x2 helpers (Blackwell dual-FMA pipe, PTX-only) ----
__device__ __forceinline__ unsigned long long pack2(float v) {
    unsigned long long r;
    asm("mov.b64 %0, {%1, %1};" : "=l"(r) : "f"(v));
    return r;
}
__device__ __forceinline__ void fma2(unsigned long long& d, unsigned long long a,
                                     unsigned long long b) {
    asm("fma.rn.f32x2 %0, %1, %2, %3;" : "=l"(d) : "l"(a), "l"(b), "l"(d));
}
__device__ __forceinline__ float2 unpack2(unsigned long long v) {
    float2 f;
    asm("mov.b64 {%0, %1}, %2;" : "=f"(f.x), "=f"(f.y) : "l"(v));
    return f;
}

// ============================================================================
// Transpose x[b][r][i] -> xT[r][i][b].
// ============================================================================
__global__ void xpose_kernel(const float* __restrict__ x) {
    const int r = blockIdx.x;
    const int b = threadIdx.x;
    float t[I_];
#pragma unroll
    for (int q = 0; q < 5; q++) {
        float4 v = reinterpret_cast<const float4*>(x + ((size_t)b * R_ + r) * I_)[q];
        t[4 * q + 0] = v.x; t[4 * q + 1] = v.y; t[4 * q + 2] = v.z; t[4 * q + 3] = v.w;
    }
#pragma unroll
    for (int i = 0; i < I_; i++)
        g_xT[((size_t)r * I_ + i) * B_ + b] = t[i];
}

// ============================================================================
// u_hat[r][c][b][o] = sum_i W[r,c,o,i] * x[b,r,i]  (fp32 compute, fp16 store)
// ============================================================================
#define CPB 8
__global__ void __launch_bounds__(128) uhat_kernel(const float* __restrict__ W) {
    const int r  = blockIdx.x / (C_ / CPB);
    const int c0 = (blockIdx.x % (C_ / CPB)) * CPB;
    __shared__ __align__(16) float sW[CPB][I_][O_];
    const int tid = threadIdx.x;

    for (int idx = tid; idx < CPB * O_ * I_; idx += 128) {
        int cc  = idx / (O_ * I_);
        int rem = idx % (O_ * I_);
        int o = rem / I_;
        int i = rem % I_;
        sW[cc][i][o] = W[(((size_t)r * C_ + c0 + cc) * O_ + o) * I_ + i];
    }

    float xr[2][I_];
#pragma unroll
    for (int i = 0; i < I_; i++) {
        xr[0][i] = g_xT[((size_t)r * I_ + i) * B_ + tid];
        xr[1][i] = g_xT[((size_t)r * I_ + i) * B_ + tid + 128];
    }
    __syncthreads();

    for (int cc = 0; cc < CPB; cc++) {
        unsigned long long acc[2][O_ / 2];
#pragma unroll
        for (int h = 0; h < 2; h++)
#pragma unroll
            for (int op = 0; op < O_ / 2; op++) acc[h][op] = 0ULL;

#pragma unroll
        for (int i = 0; i < I_; i++) {
            unsigned long long x20 = pack2(xr[0][i]);
            unsigned long long x21 = pack2(xr[1][i]);
#pragma unroll
            for (int op = 0; op < O_ / 2; op++) {
                unsigned long long w2 =
                    *reinterpret_cast<const unsigned long long*>(&sW[cc][i][2 * op]);
                fma2(acc[0][op], w2, x20);
                fma2(acc[1][op], w2, x21);
            }
        }
#pragma unroll
        for (int h = 0; h < 2; h++) {
            const int b = tid + h * 128;
            __half2 hv[O_ / 2];
#pragma unroll
            for (int op = 0; op < O_ / 2; op++) {
                float2 f = unpack2(acc[h][op]);
                hv[op] = __floats2half2_rn(f.x, f.y);
            }
            uint4* dst = reinterpret_cast<uint4*>(
                g_uhat + (((size_t)r * C_ + c0 + cc) * B_ + b) * O_);
            dst[0] = *reinterpret_cast<uint4*>(&hv[0]);
            dst[1] = *reinterpret_cast<uint4*>(&hv[4]);
        }
    }
}

// ============================================================================
// Fused per-iteration kernel. Block = (c, 16-b chunk), 512 threads.
//   phase 0: load u tile [192r][16b][16o] fp16 -> smem (96KB); softmax(logits)
//   phase 1: s = sum_r c_r * u; squash -> v  (write out if final iter)
//   phase 2: a_partial[r] = sum_{b in chunk, o} u * v  -> g_part[it][ch][r][c]
// u is read from HBM exactly ONCE per iteration.
// ============================================================================
__global__ void __launch_bounds__(512, 2) fused_kernel(float* __restrict__ out, int it) {
    const int c  = blockIdx.x % C_;
    const int ch = blockIdx.x / C_;
    const int b0 = ch * BCH;
    const int tid  = threadIdx.x;
    const int lane = tid & 31, warp = tid >> 5;

    extern __shared__ __align__(16) __half su[];   // [R_][BCH][O_] = 98304 B
    __shared__ float2 sv[BCH * 8];                 // v per (b, o-pair)
    __shared__ float  sc[R_];                      // softmax coefficients
    __shared__ float2 sred[4][128];                // r-quarter partial s
    __shared__ float  smax[6], ssum[6];

    // ---- phase 0a: issue tile load (GMEM -> SMEM) ----
    const __half* gsrc = g_uhat + ((size_t)c * B_ + b0) * O_;
    const size_t rstride = (size_t)C_ * B_ * O_;   // halves per r step
    uint4* su4 = reinterpret_cast<uint4*>(su);
#pragma unroll
    for (int k = 0; k < 12; k++) {
        int idx = tid + 512 * k;      // 6144 uint4 total; 32 per r
        int r = idx >> 5;
        int q = idx & 31;
        su4[idx] = *reinterpret_cast<const uint4*>(gsrc + r * rstride + q * 8);
    }

    // ---- phase 0b: softmax over r of the accumulated logits ----
    float lg = 0.f, e = 0.f;
    if (it > 0 && tid < R_) {
#pragma unroll
        for (int k = 0; k < NCH; k++) lg += g_part[0][k][tid][c];
        if (it == 2)
#pragma unroll
            for (int k = 0; k < NCH; k++) lg += g_part[1][k][tid][c];
        lg *= (1.f / B_);
        float m = lg;
#pragma unroll
        for (int ofs = 16; ofs; ofs >>= 1) m = fmaxf(m, __shfl_xor_sync(0xFFFFFFFFu, m, ofs));
        if (lane == 0 && warp < 6) smax[warp] = m;
    }
    __syncthreads();
    if (it > 0 && tid < R_) {
        float mm = smax[0];
#pragma unroll
        for (int w = 1; w < 6; w++) mm = fmaxf(mm, smax[w]);
        e = expf(lg - mm);
        float s = e;
#pragma unroll
        for (int ofs = 16; ofs; ofs >>= 1) s += __shfl_xor_sync(0xFFFFFFFFu, s, ofs);
        if (lane == 0 && warp < 6) ssum[warp] = s;
    }
    __syncthreads();
    if (tid < R_) {
        if (it == 0) sc[tid] = 1.f / R_;
        else {
            float tot = 0.f;
#pragma unroll
            for (int w = 0; w < 6; w++) tot += ssum[w];
            sc[tid] = e / tot;
        }
    }
    __syncthreads();   // tile + sc ready

    // ---- phase 1: s[b,o] = sum_r sc[r] * u[r,b,o], split over 4 r-quarters ----
    const __half2* su2 = reinterpret_cast<const __half2*>(su);
    const int myidx = tid & 127;          // = bl*8 + op  (half2 index within r)
    const int rq = tid >> 7;              // 0..3
    {
        float2 acc = make_float2(0.f, 0.f);
        const int r0 = rq * 48;
#pragma unroll 8
        for (int r = r0; r < r0 + 48; r++) {
            float2 u = __half22float2(su2[r * 128 + myidx]);
            float cv = sc[r];
            acc.x = fmaf(cv, u.x, acc.x);
            acc.y = fmaf(cv, u.y, acc.y);
        }
        sred[rq][myidx] = acc;
    }
    __syncthreads();

    if (tid < 128) {
        float2 s = sred[0][tid];
#pragma unroll
        for (int k = 1; k < 4; k++) { s.x += sred[k][tid].x; s.y += sred[k][tid].y; }
        // squash: norm over 16 o's = 8 consecutive op-lanes (same b)
        float n2 = s.x * s.x + s.y * s.y;
#pragma unroll
        for (int ofs = 1; ofs < 8; ofs <<= 1) n2 += __shfl_xor_sync(0xFFFFFFFFu, n2, ofs);
        float scale = sqrtf(n2) / (1.f + n2);
        s.x *= scale; s.y *= scale;
        if (it == 2) {
            const int bl = tid >> 3, op = tid & 7;
            float2* dst = reinterpret_cast<float2*>(
                out + (((size_t)(b0 + bl) * C_ + c) * O_)) + op;
            *dst = s;
        } else {
            sv[tid] = s;
        }
    }
    if (it == 2) return;
    __syncthreads();

    // ---- phase 2: a[r] = sum_{b,o} u[r,b,o] * v[b,o] (tile from SMEM) ----
    float2 vv[4];
#pragma unroll
    for (int k = 0; k < 4; k++) vv[k] = sv[lane + 32 * k];

#pragma unroll
    for (int k = 0; k < 12; k++) {
        const int r = warp + 16 * k;
        float p = 0.f;
#pragma unroll
        for (int j = 0; j < 4; j++) {
            float2 u = __half22float2(su2[r * 128 + lane + 32 * j]);
            p = fmaf(u.x, vv[j].x, p);
            p = fmaf(u.y, vv[j].y, p);
        }
#pragma unroll
        for (int ofs = 16; ofs; ofs >>= 1) p += __shfl_xor_sync(0xFFFFFFFFu, p, ofs);
        if (lane == 0) g_part[it][ch][r][c] = p;
    }
}

extern "C" void kernel_launch(void* const* d_in, const int* in_sizes, int n_in,
                              void* d_out, int out_size) {
    const float* x = (const float*)d_in[0];  // [B,R,I]
    const float* W = (const float*)d_in[1];  // [R,C,O,I]
    float* out = (float*)d_out;              // [B,C,O]

    const int smem = R_ * BCH * O_ * sizeof(__half);  // 98304
    cudaFuncSetAttribute(fused_kernel, cudaFuncAttributeMaxDynamicSharedMemorySize, smem);

    xpose_kernel<<<R_, 256>>>(x);
    uhat_kernel<<<R_ * (C_ / CPB), 128>>>(W);

    for (int it = 0; it < 3; it++)
        fused_kernel<<<C_ * NCH, 512, smem>>>(out, it);
}

// round 4
// speedup vs baseline: 1.0316x; 1.0316x over previous
#include <cuda_runtime.h>
#include <cuda_fp16.h>
#include <stdint.h>

#define B_ 256
#define R_ 192
#define C_ 96
#define O_ 16
#define I_ 20
#define BCH 16                  // batch elements per fused block
#define NCH (B_ / BCH)          // 16 chunks

// Scratch (allocation-free rule: __device__ globals)
__device__ __half g_uhat[(size_t)R_ * C_ * B_ * O_];  // [R][C][B][O] fp16 ~151MB
__device__ float  g_xT[(size_t)R_ * I_ * B_];         // [R][I][B] transposed x
__device__ float  g_part[2][NCH][R_][C_];             // agreement partials per iter

// ---- packed fp32x2 helpers (Blackwell dual-FMA pipe, PTX-only) ----
__device__ __forceinline__ unsigned long long pack2(float v) {
    unsigned long long r;
    asm("mov.b64 %0, {%1, %1};" : "=l"(r) : "f"(v));
    return r;
}
__device__ __forceinline__ void fma2(unsigned long long& d, unsigned long long a,
                                     unsigned long long b) {
    asm("fma.rn.f32x2 %0, %1, %2, %3;" : "=l"(d) : "l"(a), "l"(b), "l"(d));
}
__device__ __forceinline__ float2 unpack2(unsigned long long v) {
    float2 f;
    asm("mov.b64 {%0, %1}, %2;" : "=f"(f.x), "=f"(f.y) : "l"(v));
    return f;
}

// ---- cp.async helpers ----
__device__ __forceinline__ uint32_t smem_u32(const void* p) {
    return (uint32_t)__cvta_generic_to_shared(p);
}
__device__ __forceinline__ void cp_async16(uint32_t dst, const void* src) {
    asm volatile("cp.async.cg.shared.global [%0], [%1], 16;" :: "r"(dst), "l"(src)
                 : "memory");
}
__device__ __forceinline__ void cp_commit() {
    asm volatile("cp.async.commit_group;" ::: "memory");
}
template <int W> __device__ __forceinline__ void cp_wait() {
    asm volatile("cp.async.wait_group %0;" :: "n"(W) : "memory");
}

// ============================================================================
// Transpose x[b][r][i] -> xT[r][i][b].
// ============================================================================
__global__ void xpose_kernel(const float* __restrict__ x) {
    const int r = blockIdx.x;
    const int b = threadIdx.x;
    float t[I_];
#pragma unroll
    for (int q = 0; q < 5; q++) {
        float4 v = reinterpret_cast<const float4*>(x + ((size_t)b * R_ + r) * I_)[q];
        t[4 * q + 0] = v.x; t[4 * q + 1] = v.y; t[4 * q + 2] = v.z; t[4 * q + 3] = v.w;
    }
#pragma unroll
    for (int i = 0; i < I_; i++)
        g_xT[((size_t)r * I_ + i) * B_ + b] = t[i];
}

// ============================================================================
// u_hat[r][c][b][o] = sum_i W[r,c,o,i] * x[b,r,i]  (fp32 compute, fp16 store)
// ============================================================================
#define CPB 8
__global__ void __launch_bounds__(128) uhat_kernel(const float* __restrict__ W) {
    const int r  = blockIdx.x / (C_ / CPB);
    const int c0 = (blockIdx.x % (C_ / CPB)) * CPB;
    __shared__ __align__(16) float sW[CPB][I_][O_];
    const int tid = threadIdx.x;

    for (int idx = tid; idx < CPB * O_ * I_; idx += 128) {
        int cc  = idx / (O_ * I_);
        int rem = idx % (O_ * I_);
        int o = rem / I_;
        int i = rem % I_;
        sW[cc][i][o] = W[(((size_t)r * C_ + c0 + cc) * O_ + o) * I_ + i];
    }

    float xr[2][I_];
#pragma unroll
    for (int i = 0; i < I_; i++) {
        xr[0][i] = g_xT[((size_t)r * I_ + i) * B_ + tid];
        xr[1][i] = g_xT[((size_t)r * I_ + i) * B_ + tid + 128];
    }
    __syncthreads();

    for (int cc = 0; cc < CPB; cc++) {
        unsigned long long acc[2][O_ / 2];
#pragma unroll
        for (int h = 0; h < 2; h++)
#pragma unroll
            for (int op = 0; op < O_ / 2; op++) acc[h][op] = 0ULL;

#pragma unroll
        for (int i = 0; i < I_; i++) {
            unsigned long long x20 = pack2(xr[0][i]);
            unsigned long long x21 = pack2(xr[1][i]);
#pragma unroll
            for (int op = 0; op < O_ / 2; op++) {
                unsigned long long w2 =
                    *reinterpret_cast<const unsigned long long*>(&sW[cc][i][2 * op]);
                fma2(acc[0][op], w2, x20);
                fma2(acc[1][op], w2, x21);
            }
        }
#pragma unroll
        for (int h = 0; h < 2; h++) {
            const int b = tid + h * 128;
            __half2 hv[O_ / 2];
#pragma unroll
            for (int op = 0; op < O_ / 2; op++) {
                float2 f = unpack2(acc[h][op]);
                hv[op] = __floats2half2_rn(f.x, f.y);
            }
            uint4* dst = reinterpret_cast<uint4*>(
                g_uhat + (((size_t)r * C_ + c0 + cc) * B_ + b) * O_);
            dst[0] = *reinterpret_cast<uint4*>(&hv[0]);
            dst[1] = *reinterpret_cast<uint4*>(&hv[4]);
        }
    }
}

// ============================================================================
// Fused per-iteration kernel. Block = (c, 16-b chunk), 512 threads.
//   tile load: 6 cp.async commit-groups (32 r's each), consumed in order by
//   phase 1 so DRAM latency overlaps softmax + s-accumulation.
//   phase 1: s = sum_r c_r * u; squash -> v  (write out if final iter)
//   phase 2: a_partial[r] = sum_{b,o} u * v   (tile re-read from SMEM)
// u_hat is read from HBM exactly ONCE per iteration.
// ============================================================================
__global__ void __launch_bounds__(512, 2) fused_kernel(float* __restrict__ out, int it) {
    const int c  = blockIdx.x % C_;
    const int ch = blockIdx.x / C_;
    const int b0 = ch * BCH;
    const int tid  = threadIdx.x;
    const int lane = tid & 31, warp = tid >> 5;

    extern __shared__ __align__(16) __half su[];   // [R_][BCH][O_] = 98304 B
    __shared__ float2 sv[BCH * 8];                 // v per (b, o-pair)
    __shared__ float  sc[R_];                      // softmax coefficients
    __shared__ float2 sred[4][128];                // r-quarter partial s
    __shared__ float  smax[6], ssum[6];

    // ---- issue tile load: 6 chunks x (1024 uint4), 2 cp.async per thread ----
    const __half* gsrc = g_uhat + ((size_t)c * B_ + b0) * O_;
    const size_t rstride = (size_t)C_ * B_ * O_;   // halves per r step
    const uint32_t sbase = smem_u32(su);
#pragma unroll
    for (int j = 0; j < 6; j++) {
#pragma unroll
        for (int m = 0; m < 2; m++) {
            int idx = j * 1024 + tid + 512 * m;
            int r = idx >> 5;
            int q = idx & 31;
            cp_async16(sbase + idx * 16, gsrc + (size_t)r * rstride + q * 8);
        }
        cp_commit();
    }

    // ---- softmax over r (runs while loads are in flight) ----
    float lg = 0.f, e = 0.f;
    if (it > 0 && tid < R_) {
#pragma unroll
        for (int k = 0; k < NCH; k++) lg += g_part[0][k][tid][c];
        if (it == 2)
#pragma unroll
            for (int k = 0; k < NCH; k++) lg += g_part[1][k][tid][c];
        lg *= (1.f / B_);
        float m = lg;
#pragma unroll
        for (int ofs = 16; ofs; ofs >>= 1) m = fmaxf(m, __shfl_xor_sync(0xFFFFFFFFu, m, ofs));
        if (lane == 0 && warp < 6) smax[warp] = m;
    }
    __syncthreads();
    if (it > 0 && tid < R_) {
        float mm = smax[0];
#pragma unroll
        for (int w = 1; w < 6; w++) mm = fmaxf(mm, smax[w]);
        e = expf(lg - mm);
        float s = e;
#pragma unroll
        for (int ofs = 16; ofs; ofs >>= 1) s += __shfl_xor_sync(0xFFFFFFFFu, s, ofs);
        if (lane == 0 && warp < 6) ssum[warp] = s;
    }
    __syncthreads();
    if (tid < R_) {
        if (it == 0) sc[tid] = 1.f / R_;
        else {
            float tot = 0.f;
#pragma unroll
            for (int w = 0; w < 6; w++) tot += ssum[w];
            sc[tid] = e / tot;
        }
    }
    __syncthreads();   // sc ready

    // ---- phase 1: s[b,o] = sum_r sc[r]*u[r,b,o], chunk-pipelined over r ----
    const __half2* su2 = reinterpret_cast<const __half2*>(su);
    const int myidx = tid & 127;          // half2 index within an r row
    const int rq = tid >> 7;              // 0..3: r sub-chunk within each chunk
    float2 acc = make_float2(0.f, 0.f);

#define PROC_CHUNK(J, W)                                                       \
    do {                                                                       \
        cp_wait<W>();                                                          \
        __syncthreads();                                                       \
        _Pragma("unroll")                                                      \
        for (int rr = 0; rr < 8; rr++) {                                       \
            int r = 32 * (J) + 8 * rq + rr;                                    \
            float2 u = __half22float2(su2[r * 128 + myidx]);                   \
            float cv = sc[r];                                                  \
            acc.x = fmaf(cv, u.x, acc.x);                                      \
            acc.y = fmaf(cv, u.y, acc.y);                                      \
        }                                                                      \
    } while (0)

    PROC_CHUNK(0, 5);
    PROC_CHUNK(1, 4);
    PROC_CHUNK(2, 3);
    PROC_CHUNK(3, 2);
    PROC_CHUNK(4, 1);
    PROC_CHUNK(5, 0);
#undef PROC_CHUNK

    sred[rq][myidx] = acc;
    __syncthreads();

    if (tid < 128) {
        float2 s = sred[0][tid];
#pragma unroll
        for (int k = 1; k < 4; k++) { s.x += sred[k][tid].x; s.y += sred[k][tid].y; }
        // squash: norm over 16 o's = 8 consecutive op-lanes (same b)
        float n2 = s.x * s.x + s.y * s.y;
#pragma unroll
        for (int ofs = 1; ofs < 8; ofs <<= 1) n2 += __shfl_xor_sync(0xFFFFFFFFu, n2, ofs);
        float scale = sqrtf(n2) / (1.f + n2);
        s.x *= scale; s.y *= scale;
        if (it == 2) {
            const int bl = tid >> 3, op = tid & 7;
            float2* dst = reinterpret_cast<float2*>(
                out + (((size_t)(b0 + bl) * C_ + c) * O_)) + op;
            *dst = s;
        } else {
            sv[tid] = s;
        }
    }
    if (it == 2) return;
    __syncthreads();

    // ---- phase 2: a[r] = sum_{b,o} u[r,b,o] * v[b,o] (tile from SMEM) ----
    float2 vv[4];
#pragma unroll
    for (int k = 0; k < 4; k++) vv[k] = sv[lane + 32 * k];

#pragma unroll
    for (int k = 0; k < 12; k++) {
        const int r = warp + 16 * k;
        float p = 0.f;
#pragma unroll
        for (int j = 0; j < 4; j++) {
            float2 u = __half22float2(su2[r * 128 + lane + 32 * j]);
            p = fmaf(u.x, vv[j].x, p);
            p = fmaf(u.y, vv[j].y, p);
        }
#pragma unroll
        for (int ofs = 16; ofs; ofs >>= 1) p += __shfl_xor_sync(0xFFFFFFFFu, p, ofs);
        if (lane == 0) g_part[it][ch][r][c] = p;
    }
}

extern "C" void kernel_launch(void* const* d_in, const int* in_sizes, int n_in,
                              void* d_out, int out_size) {
    const float* x = (const float*)d_in[0];  // [B,R,I]
    const float* W = (const float*)d_in[1];  // [R,C,O,I]
    float* out = (float*)d_out;              // [B,C,O]

    const int smem = R_ * BCH * O_ * sizeof(__half);  // 98304
    cudaFuncSetAttribute(fused_kernel, cudaFuncAttributeMaxDynamicSharedMemorySize, smem);

    xpose_kernel<<<R_, 256>>>(x);
    uhat_kernel<<<R_ * (C_ / CPB), 128>>>(W);

    for (int it = 0; it < 3; it++)
        fused_kernel<<<C_ * NCH, 512, smem>>>(out, it);
}

// round 6
// speedup vs baseline: 1.2731x; 1.2341x over previous
#include <cuda_runtime.h>
#include <cuda_fp16.h>
#include <stdint.h>

#define B_ 256
#define R_ 192
#define C_ 96
#define O_ 16
#define I_ 20
#define BCH 8                   // batch elements per tile
#define NCH (B_ / BCH)          // 32 chunks
#define TILES (C_ * NCH)        // 3072
#define GRID 304                // persistent CTAs (2/SM on 152 SMs)
#define TILE_U4 (R_ * BCH * O_ / 8)   // 3072 uint4 = 48KB per tile

// Scratch (allocation-free rule: __device__ globals)
__device__ __half g_uhat[(size_t)R_ * C_ * B_ * O_];  // [R][C][B][O] fp16 ~151MB
__device__ float  g_xT[(size_t)R_ * I_ * B_];         // [R][I][B] transposed x
__device__ float  g_part[2][C_][R_][NCH];             // agreement partials

// ---- packed fp32x2 helpers ----
__device__ __forceinline__ unsigned long long pack2(float v) {
    unsigned long long r;
    asm("mov.b64 %0, {%1, %1};" : "=l"(r) : "f"(v));
    return r;
}
__device__ __forceinline__ void fma2(unsigned long long& d, unsigned long long a,
                                     unsigned long long b) {
    asm("fma.rn.f32x2 %0, %1, %2, %3;" : "=l"(d) : "l"(a), "l"(b), "l"(d));
}
__device__ __forceinline__ float2 unpack2(unsigned long long v) {
    float2 f;
    asm("mov.b64 {%0, %1}, %2;" : "=f"(f.x), "=f"(f.y) : "l"(v));
    return f;
}

// ---- cp.async helpers ----
__device__ __forceinline__ uint32_t smem_u32(const void* p) {
    return (uint32_t)__cvta_generic_to_shared(p);
}
__device__ __forceinline__ void cp_async16(uint32_t dst, const void* src) {
    asm volatile("cp.async.cg.shared.global [%0], [%1], 16;" :: "r"(dst), "l"(src)
                 : "memory");
}
__device__ __forceinline__ void cp_commit() {
    asm volatile("cp.async.commit_group;" ::: "memory");
}
template <int W> __device__ __forceinline__ void cp_wait() {
    asm volatile("cp.async.wait_group %0;" :: "n"(W) : "memory");
}

// ============================================================================
// Transpose x[b][r][i] -> xT[r][i][b].
// ============================================================================
__global__ void xpose_kernel(const float* __restrict__ x) {
    const int r = blockIdx.x;
    const int b = threadIdx.x;
    float t[I_];
#pragma unroll
    for (int q = 0; q < 5; q++) {
        float4 v = reinterpret_cast<const float4*>(x + ((size_t)b * R_ + r) * I_)[q];
        t[4 * q + 0] = v.x; t[4 * q + 1] = v.y; t[4 * q + 2] = v.z; t[4 * q + 3] = v.w;
    }
#pragma unroll
    for (int i = 0; i < I_; i++)
        g_xT[((size_t)r * I_ + i) * B_ + b] = t[i];
}

// ============================================================================
// u_hat[r][c][b][o] = sum_i W[r,c,o,i] * x[b,r,i]  (fp32 compute, fp16 store)
// ============================================================================
#define CPB 8
__global__ void __launch_bounds__(128) uhat_kernel(const float* __restrict__ W) {
    const int r  = blockIdx.x / (C_ / CPB);
    const int c0 = (blockIdx.x % (C_ / CPB)) * CPB;
    __shared__ __align__(16) float sW[CPB][I_][O_];
    const int tid = threadIdx.x;

    for (int idx = tid; idx < CPB * O_ * I_; idx += 128) {
        int cc  = idx / (O_ * I_);
        int rem = idx % (O_ * I_);
        int o = rem / I_;
        int i = rem % I_;
        sW[cc][i][o] = W[(((size_t)r * C_ + c0 + cc) * O_ + o) * I_ + i];
    }

    float xr[2][I_];
#pragma unroll
    for (int i = 0; i < I_; i++) {
        xr[0][i] = g_xT[((size_t)r * I_ + i) * B_ + tid];
        xr[1][i] = g_xT[((size_t)r * I_ + i) * B_ + tid + 128];
    }
    __syncthreads();

    for (int cc = 0; cc < CPB; cc++) {
        unsigned long long acc[2][O_ / 2];
#pragma unroll
        for (int h = 0; h < 2; h++)
#pragma unroll
            for (int op = 0; op < O_ / 2; op++) acc[h][op] = 0ULL;

#pragma unroll
        for (int i = 0; i < I_; i++) {
            unsigned long long x20 = pack2(xr[0][i]);
            unsigned long long x21 = pack2(xr[1][i]);
#pragma unroll
            for (int op = 0; op < O_ / 2; op++) {
                unsigned long long w2 =
                    *reinterpret_cast<const unsigned long long*>(&sW[cc][i][2 * op]);
                fma2(acc[0][op], w2, x20);
                fma2(acc[1][op], w2, x21);
            }
        }
#pragma unroll
        for (int h = 0; h < 2; h++) {
            const int b = tid + h * 128;
            __half2 hv[O_ / 2];
#pragma unroll
            for (int op = 0; op < O_ / 2; op++) {
                float2 f = unpack2(acc[h][op]);
                hv[op] = __floats2half2_rn(f.x, f.y);
            }
            uint4* dst = reinterpret_cast<uint4*>(
                g_uhat + (((size_t)r * C_ + c0 + cc) * B_ + b) * O_);
            dst[0] = *reinterpret_cast<uint4*>(&hv[0]);
            dst[1] = *reinterpret_cast<uint4*>(&hv[4]);
        }
    }
}

// ============================================================================
// Persistent fused routing kernel. 304 CTAs x 256 threads, double-buffered
// 48KB tiles [192r][8b][16o] fp16 (16 uint4 per r). Per tile:
//   prefetch next tile (cp.async) -> softmax (overlaps) -> wait -> phase1
//   (s+squash) -> phase2 (agreement partials from SMEM).
// ============================================================================
__global__ void __launch_bounds__(256, 2) fused_kernel(float* __restrict__ out, int it) {
    extern __shared__ __align__(16) uint4 su4[];   // 2 * TILE_U4
    __shared__ float2 sred[4][64];
    __shared__ float2 sv[64];                      // v: [8 b][8 o-pairs]
    __shared__ float  sc[R_];
    __shared__ float  smax[6], ssum[6];

    const int tid = threadIdx.x;
    const int lane = tid & 31, warp = tid >> 5;
    const size_t rstride = (size_t)C_ * B_ * O_;   // halves per r step

    // ---- prologue: issue first tile into buffer 0 ----
    {
        const int t0 = blockIdx.x;
        const int c = t0 >> 5, ch = t0 & 31;
        const __half* gsrc = g_uhat + ((size_t)c * B_ + ch * BCH) * O_;
        const uint32_t sb = smem_u32(su4);
#pragma unroll
        for (int m = 0; m < 12; m++) {
            int idx = tid + 256 * m;
            int r = idx >> 4, q = idx & 15;
            cp_async16(sb + idx * 16, gsrc + (size_t)r * rstride + q * 8);
        }
        cp_commit();
    }

    int p = 0;
    for (int t = blockIdx.x; t < TILES; t += GRID, p ^= 1) {
        const int c = t >> 5, ch = t & 31;
        const int b0 = ch * BCH;
        const int tn = t + GRID;
        const bool has_next = tn < TILES;

        // ---- issue next tile into the other buffer ----
        if (has_next) {
            const int cn = tn >> 5, chn = tn & 31;
            const __half* gsrc = g_uhat + ((size_t)cn * B_ + chn * BCH) * O_;
            const uint32_t sb = smem_u32(su4 + (p ^ 1) * TILE_U4);
#pragma unroll
            for (int m = 0; m < 12; m++) {
                int idx = tid + 256 * m;
                int r = idx >> 4, q = idx & 15;
                cp_async16(sb + idx * 16, gsrc + (size_t)r * rstride + q * 8);
            }
            cp_commit();
        }

        // ---- softmax over r (overlaps in-flight loads) ----
        if (it > 0) {
            float lg = 0.f, e = 0.f;
            if (tid < R_) {
                const float4* q0 = reinterpret_cast<const float4*>(
                    &g_part[0][c][tid][0]);
#pragma unroll
                for (int j = 0; j < NCH / 4; j++) {
                    float4 v = q0[j];
                    lg += v.x + v.y + v.z + v.w;
                }
                if (it == 2) {
                    const float4* q1 = reinterpret_cast<const float4*>(
                        &g_part[1][c][tid][0]);
#pragma unroll
                    for (int j = 0; j < NCH / 4; j++) {
                        float4 v = q1[j];
                        lg += v.x + v.y + v.z + v.w;
                    }
                }
                lg *= (1.f / B_);
                float m = lg;
#pragma unroll
                for (int ofs = 16; ofs; ofs >>= 1)
                    m = fmaxf(m, __shfl_xor_sync(0xFFFFFFFFu, m, ofs));
                if (lane == 0) smax[warp] = m;
            }
            __syncthreads();
            if (tid < R_) {
                float mm = smax[0];
#pragma unroll
                for (int w = 1; w < 6; w++) mm = fmaxf(mm, smax[w]);
                e = expf(lg - mm);
                float s = e;
#pragma unroll
                for (int ofs = 16; ofs; ofs >>= 1)
                    s += __shfl_xor_sync(0xFFFFFFFFu, s, ofs);
                if (lane == 0) ssum[warp] = s;
            }
            __syncthreads();
            if (tid < R_) {
                float tot = 0.f;
#pragma unroll
                for (int w = 0; w < 6; w++) tot += ssum[w];
                sc[tid] = e / tot;
            }
        } else {
            if (tid < R_) sc[tid] = 1.f / R_;
        }

        // ---- wait for current tile ----
        if (has_next) cp_wait<1>(); else cp_wait<0>();
        __syncthreads();

        const uint4*   sub = su4 + p * TILE_U4;
        const __half2* su2 = reinterpret_cast<const __half2*>(sub);

        // ---- phase 1: s[b,o] = sum_r sc[r]*u[r,b,o] ----
        {
            const int myidx = tid & 63;   // half2 index within r row (64 per r)
            const int rq = tid >> 6;      // 0..3
            float2 acc = make_float2(0.f, 0.f);
            const int r0 = rq * 48;
#pragma unroll 8
            for (int r = r0; r < r0 + 48; r++) {
                float2 u = __half22float2(su2[r * 64 + myidx]);
                float cv = sc[r];
                acc.x = fmaf(cv, u.x, acc.x);
                acc.y = fmaf(cv, u.y, acc.y);
            }
            sred[rq][myidx] = acc;
        }
        __syncthreads();

        if (tid < 64) {
            float2 s = sred[0][tid];
#pragma unroll
            for (int k = 1; k < 4; k++) { s.x += sred[k][tid].x; s.y += sred[k][tid].y; }
            float n2 = s.x * s.x + s.y * s.y;
#pragma unroll
            for (int ofs = 1; ofs < 8; ofs <<= 1)
                n2 += __shfl_xor_sync(0xFFFFFFFFu, n2, ofs);
            float scale = sqrtf(n2) / (1.f + n2);
            s.x *= scale; s.y *= scale;
            if (it == 2) {
                const int bl = tid >> 3, op = tid & 7;
                float2* dst = reinterpret_cast<float2*>(
                    out + (((size_t)(b0 + bl) * C_ + c) * O_)) + op;
                *dst = s;
            } else {
                sv[tid] = s;   // sv[b*8 + op]
            }
        }
        __syncthreads();

        // ---- phase 2: a[r] = sum_{b,o} u[r,b,o]*v[b,o] (tile from SMEM) ----
        // Each r row = 16 uint4; lanes 0-15 handle r0, lanes 16-31 handle r1.
        // uint4 q covers (b = q>>1, o-half = q&1) -> v entries sv[q*4 + j].
        if (it != 2) {
            const int q  = lane & 15;
            const int rh = lane >> 4;     // 0 or 1
            float2 vv[4];
#pragma unroll
            for (int j = 0; j < 4; j++) vv[j] = sv[q * 4 + j];

#pragma unroll 4
            for (int k = 0; k < 12; k++) {
                const int r = warp + 8 * (2 * k + rh);
                uint4 u4 = sub[r * 16 + q];
                const __half2* h = reinterpret_cast<const __half2*>(&u4);
                float pacc = 0.f;
#pragma unroll
                for (int j = 0; j < 4; j++) {
                    float2 uf = __half22float2(h[j]);
                    pacc = fmaf(uf.x, vv[j].x, pacc);
                    pacc = fmaf(uf.y, vv[j].y, pacc);
                }
#pragma unroll
                for (int ofs = 8; ofs; ofs >>= 1)
                    pacc += __shfl_xor_sync(0xFFFFFFFFu, pacc, ofs);
                if ((lane & 15) == 0) g_part[it][c][r][ch] = pacc;
            }
        }
        __syncthreads();   // protect buffers/smem before next tile's issue
    }
}

extern "C" void kernel_launch(void* const* d_in, const int* in_sizes, int n_in,
                              void* d_out, int out_size) {
    const float* x = (const float*)d_in[0];  // [B,R,I]
    const float* W = (const float*)d_in[1];  // [R,C,O,I]
    float* out = (float*)d_out;              // [B,C,O]

    const int smem = 2 * TILE_U4 * sizeof(uint4);   // 98304
    cudaFuncSetAttribute(fused_kernel, cudaFuncAttributeMaxDynamicSharedMemorySize, smem);

    xpose_kernel<<<R_, 256>>>(x);
    uhat_kernel<<<R_ * (C_ / CPB), 128>>>(W);

    for (int it = 0; it < 3; it++)
        fused_kernel<<<GRID, 256, smem>>>(out, it);
}